// round 14
// baseline (speedup 1.0000x reference)
#include <cuda_runtime.h>
#include <cuda_bf16.h>
#include <math.h>
#include <stdint.h>

#define N_NODES 20000
#define E_MAX   320000

// ---------------- device scratch ----------------------------------------------
__device__ float g_h  [N_NODES * 512];
__device__ float g_as [N_NODES * 4];
__device__ float g_ad [N_NODES * 4];
__device__ int   g_deg[N_NODES];
__device__ int   g_off[N_NODES + 1];
__device__ int   g_cur[N_NODES];
__device__ int   g_csr[E_MAX];
__device__ __nv_bfloat16 g_ah [N_NODES * 256];  // split activations ping (hi)
__device__ __nv_bfloat16 g_al [N_NODES * 256];  // split activations ping (lo)
__device__ __nv_bfloat16 g_ah2[N_NODES * 128];  // split activations pong (hi)
__device__ __nv_bfloat16 g_al2[N_NODES * 128];  // split activations pong (lo)
__device__ __nv_bfloat16 g_bh[512 * 256];       // split transposed weights (hi)
__device__ __nv_bfloat16 g_bl[512 * 256];       // split transposed weights (lo)

// ---------------- warp MMA helpers (baseline PTX: ldmatrix + mma.sync) --------
__device__ __forceinline__ uint32_t smem_u32(const void* p) {
    uint32_t a;
    asm("{ .reg .u64 t; cvta.to.shared.u64 t, %1; cvt.u32.u64 %0, t; }" : "=r"(a) : "l"(p));
    return a;
}
__device__ __forceinline__ void ldsm_x4(uint32_t* d, uint32_t addr) {
    asm volatile("ldmatrix.sync.aligned.m8n8.x4.shared.b16 {%0,%1,%2,%3}, [%4];"
                 : "=r"(d[0]), "=r"(d[1]), "=r"(d[2]), "=r"(d[3]) : "r"(addr));
}
__device__ __forceinline__ void ldsm_x2(uint32_t* d, uint32_t addr) {
    asm volatile("ldmatrix.sync.aligned.m8n8.x2.shared.b16 {%0,%1}, [%2];"
                 : "=r"(d[0]), "=r"(d[1]) : "r"(addr));
}
__device__ __forceinline__ void mma_bf16(float* c, const uint32_t* a, const uint32_t* b) {
    asm volatile("mma.sync.aligned.m16n8k16.row.col.f32.bf16.bf16.f32 "
                 "{%0,%1,%2,%3}, {%4,%5,%6,%7}, {%8,%9}, {%0,%1,%2,%3};"
                 : "+f"(c[0]), "+f"(c[1]), "+f"(c[2]), "+f"(c[3])
                 : "r"(a[0]), "r"(a[1]), "r"(a[2]), "r"(a[3]), "r"(b[0]), "r"(b[1]));
}
__device__ __forceinline__ uint32_t pack_bf16(__nv_bfloat16 a, __nv_bfloat16 b) {
    __nv_bfloat162 t = __halves2bfloat162(a, b);
    return *reinterpret_cast<uint32_t*>(&t);
}

// ---------------- CSR build ----------------------------------------------------
__global__ void zero_deg_kernel(int N) {
    int i = blockIdx.x * blockDim.x + threadIdx.x;
    if (i < N) g_deg[i] = 0;
}
__global__ void hist_kernel(const int* __restrict__ dst, int E) {
    int i = blockIdx.x * blockDim.x + threadIdx.x;
    if (i < E) atomicAdd(&g_deg[dst[i]], 1);
}
__global__ void scan_kernel(int N) {
    __shared__ int sh[1024];
    int tid = threadIdx.x;
    int per = (N + 1023) >> 10;
    int base = tid * per;
    int sum = 0;
    for (int i = 0; i < per; i++) { int idx = base + i; if (idx < N) sum += g_deg[idx]; }
    sh[tid] = sum;
    __syncthreads();
    for (int off = 1; off < 1024; off <<= 1) {
        int v = (tid >= off) ? sh[tid - off] : 0;
        __syncthreads();
        sh[tid] += v;
        __syncthreads();
    }
    int run = tid ? sh[tid - 1] : 0;
    for (int i = 0; i < per; i++) {
        int idx = base + i;
        if (idx < N) { g_off[idx] = run; g_cur[idx] = run; run += g_deg[idx]; }
    }
    if (tid == 1023) g_off[N] = sh[1023];
}
__global__ void scatter_kernel(const int* __restrict__ src, const int* __restrict__ dst, int E) {
    int i = blockIdx.x * blockDim.x + threadIdx.x;
    if (i < E) {
        int p = atomicAdd(&g_cur[dst[i]], 1);
        g_csr[p] = src[i];
    }
}

// ---------------- split-bf16 conversions ---------------------------------------
__global__ void split_kernel(const float* __restrict__ in, __nv_bfloat16* __restrict__ hi,
                             __nv_bfloat16* __restrict__ lo, int n)
{
    int i = blockIdx.x * blockDim.x + threadIdx.x;
    if (i >= n) return;
    float x = in[i];
    __nv_bfloat16 h = __float2bfloat16(x);
    hi[i] = h;
    lo[i] = __float2bfloat16(x - __bfloat162float(h));
}
// W [K,N] row-major -> Wt hi/lo [N,K]
__global__ void splitT_kernel(const float* __restrict__ W, __nv_bfloat16* __restrict__ hi,
                              __nv_bfloat16* __restrict__ lo, int K, int N)
{
    int i = blockIdx.x * blockDim.x + threadIdx.x;
    if (i >= K * N) return;
    int n = i / K, k = i - n * K;
    float x = W[(size_t)k * N + n];
    __nv_bfloat16 h = __float2bfloat16(x);
    hi[i] = h;
    lo[i] = __float2bfloat16(x - __bfloat162float(h));
}

// ---------------- split-bf16 tensor-core GEMM (mma.sync) -----------------------
// C[M,Ntot] = (Ah+Al)[M,K] @ (Bh+Bl)^T   (B stored [Ntot,K] K-major)
// Block tile 128Mx64Nx64K, 8 warps (4x2), warp tile 32x32.
// Output: f32 C (if non-null) and/or split-bf16 Ch/Cl (if non-null).
// act: 0 none, 1 relu, 2 sigmoid
#define GLD 72
__global__ __launch_bounds__(256)
void mma_gemm_kernel(const __nv_bfloat16* __restrict__ Ah, const __nv_bfloat16* __restrict__ Al,
                     const __nv_bfloat16* __restrict__ Bh, const __nv_bfloat16* __restrict__ Bl,
                     const float* __restrict__ bias, float* __restrict__ C,
                     __nv_bfloat16* __restrict__ Ch, __nv_bfloat16* __restrict__ Cl,
                     int M, int Ntot, int K, int act)
{
    extern __shared__ __nv_bfloat16 sm[];
    __nv_bfloat16* sAh = sm;
    __nv_bfloat16* sAl = sAh + 128 * GLD;
    __nv_bfloat16* sBh = sAl + 128 * GLD;
    __nv_bfloat16* sBl = sBh + 64 * GLD;

    int tid = threadIdx.x, lane = tid & 31, warp = tid >> 5;
    int wm = warp >> 1, wn = warp & 1;
    int bm = blockIdx.y * 128, bn = blockIdx.x * 64;

    uint32_t aAh = smem_u32(sAh), aAl = smem_u32(sAl);
    uint32_t aBh = smem_u32(sBh), aBl = smem_u32(sBl);

    float acc[2][4][4];
#pragma unroll
    for (int mt = 0; mt < 2; mt++)
#pragma unroll
        for (int nt = 0; nt < 4; nt++)
#pragma unroll
            for (int q = 0; q < 4; q++) acc[mt][nt][q] = 0.f;

    for (int kc = 0; kc < K; kc += 64) {
        for (int i = tid; i < 2048; i += 256) {
            int row = i >> 4, seg = (i & 15) << 2;
            int m = bm + row, k = kc + seg;
            uint2 hv = make_uint2(0u, 0u), lv = make_uint2(0u, 0u);
            if (m < M) {
                hv = *(const uint2*)(Ah + (size_t)m * K + k);
                lv = *(const uint2*)(Al + (size_t)m * K + k);
            }
            *(uint2*)&sAh[row * GLD + seg] = hv;
            *(uint2*)&sAl[row * GLD + seg] = lv;
        }
        for (int i = tid; i < 1024; i += 256) {
            int row = i >> 4, seg = (i & 15) << 2;
            int n = bn + row, k = kc + seg;
            *(uint2*)&sBh[row * GLD + seg] = *(const uint2*)(Bh + (size_t)n * K + k);
            *(uint2*)&sBl[row * GLD + seg] = *(const uint2*)(Bl + (size_t)n * K + k);
        }
        __syncthreads();

#pragma unroll
        for (int ks = 0; ks < 64; ks += 16) {
            uint32_t ah[2][4], al[2][4];
            int ar = lane & 15, ac = (lane >> 4) << 3;
#pragma unroll
            for (int mt = 0; mt < 2; mt++) {
                uint32_t off = (uint32_t)((wm * 32 + mt * 16 + ar) * GLD + ks + ac) * 2;
                ldsm_x4(ah[mt], aAh + off);
                ldsm_x4(al[mt], aAl + off);
            }
            uint32_t bh[4][2], bl[4][2];
            int br = lane & 7, bc = ((lane >> 3) & 1) << 3;
#pragma unroll
            for (int nt = 0; nt < 4; nt++) {
                uint32_t off = (uint32_t)((wn * 32 + nt * 8 + br) * GLD + ks + bc) * 2;
                ldsm_x2(bh[nt], aBh + off);
                ldsm_x2(bl[nt], aBl + off);
            }
#pragma unroll
            for (int mt = 0; mt < 2; mt++)
#pragma unroll
                for (int nt = 0; nt < 4; nt++) {
                    mma_bf16(acc[mt][nt], ah[mt], bh[nt]);
                    mma_bf16(acc[mt][nt], ah[mt], bl[nt]);
                    mma_bf16(acc[mt][nt], al[mt], bh[nt]);
                }
        }
        __syncthreads();
    }

    int rb = bm + wm * 32 + (lane >> 2);
    int cb = bn + wn * 32 + ((lane & 3) << 1);
#pragma unroll
    for (int mt = 0; mt < 2; mt++) {
        int r = rb + mt * 16;
#pragma unroll
        for (int nt = 0; nt < 4; nt++) {
            int c = cb + nt * 8;
            float bx = bias ? bias[c] : 0.f, by = bias ? bias[c + 1] : 0.f;
#pragma unroll
            for (int half = 0; half < 2; half++) {
                int rr = r + half * 8;
                if (rr >= M) continue;
                float v0 = acc[mt][nt][half * 2 + 0] + bx;
                float v1 = acc[mt][nt][half * 2 + 1] + by;
                if (act == 1)      { v0 = fmaxf(v0, 0.f); v1 = fmaxf(v1, 0.f); }
                else if (act == 2) { v0 = 1.f / (1.f + expf(-v0)); v1 = 1.f / (1.f + expf(-v1)); }
                if (C) *(float2*)(C + (size_t)rr * Ntot + c) = make_float2(v0, v1);
                if (Ch) {
                    __nv_bfloat16 h0 = __float2bfloat16(v0), h1 = __float2bfloat16(v1);
                    __nv_bfloat16 l0 = __float2bfloat16(v0 - __bfloat162float(h0));
                    __nv_bfloat16 l1 = __float2bfloat16(v1 - __bfloat162float(h1));
                    *(uint32_t*)(Ch + (size_t)rr * Ntot + c) = pack_bf16(h0, h1);
                    *(uint32_t*)(Cl + (size_t)rr * Ntot + c) = pack_bf16(l0, l1);
                }
            }
        }
    }
}

// ---------------- attention coefficient precompute ----------------------------
__global__ void alpha_kernel(const float* __restrict__ h, const float* __restrict__ a_src,
                             const float* __restrict__ a_dst, float* __restrict__ as_,
                             float* __restrict__ ad_, int N, int H)
{
    int gw = (blockIdx.x * blockDim.x + threadIdx.x) >> 5;
    int lane = threadIdx.x & 31;
    if (gw >= N * H) return;
    int n = gw / H, hh = gw - n * H;
    const float4* hp = (const float4*)(h + ((size_t)n * H + hh) * 128);
    const float4* sp = (const float4*)(a_src + hh * 128);
    const float4* dp = (const float4*)(a_dst + hh * 128);
    float4 v = hp[lane], sv = sp[lane], dv = dp[lane];
    float s = v.x * sv.x + v.y * sv.y + v.z * sv.z + v.w * sv.w;
    float d = v.x * dv.x + v.y * dv.y + v.z * dv.z + v.w * dv.w;
#pragma unroll
    for (int o = 16; o; o >>= 1) {
        s += __shfl_xor_sync(0xFFFFFFFFu, s, o);
        d += __shfl_xor_sync(0xFFFFFFFFu, d, o);
    }
    if (lane == 0) { as_[n * H + hh] = s; ad_[n * H + hh] = d; }
}

// ---------------- fused GAT aggregation (one warp per dst node) ----------------
// Edge loop unrolled x2 (two edges' gathers in flight). Epilogue emits
// split-bf16 (hi/lo) directly for the next GEMM's A operand.
template<int H, bool DO_BN>
__global__ void gat_agg_kernel(const float* __restrict__ h,
                               const float* __restrict__ as_, const float* __restrict__ ad_,
                               const float* __restrict__ bias,
                               const float* __restrict__ bg, const float* __restrict__ bb,
                               const float* __restrict__ bm_, const float* __restrict__ bv,
                               __nv_bfloat16* __restrict__ outh,
                               __nv_bfloat16* __restrict__ outl, int N)
{
    int d = (blockIdx.x * blockDim.x + threadIdx.x) >> 5;
    int lane = threadIdx.x & 31;
    if (d >= N) return;

    float asd[H], add[H];
    if (H == 4) {
        float4 t = ((const float4*)as_)[d];
        asd[0] = t.x; asd[1] = t.y; asd[2] = t.z; asd[3] = t.w;
        t = ((const float4*)ad_)[d];
        add[0] = t.x; add[1] = t.y; add[2] = t.z; add[3] = t.w;
    } else {
        asd[0] = as_[d]; add[0] = ad_[d];
    }

    float acc[H][4];
    float denl[H];
#pragma unroll
    for (int k = 0; k < H; k++) {
        denl[k] = 0.f;
#pragma unroll
        for (int c = 0; c < 4; c++) acc[k][c] = 0.f;
    }

    int r0 = g_off[d], r1 = g_off[d + 1];
    for (int base = r0; base < r1; base += 32) {
        int e = base + lane;
        int s = 0;
        float ex[H];
        if (e < r1) {
            s = g_csr[e];
            float av[H];
            if (H == 4) {
                float4 t = ((const float4*)as_)[s];
                av[0] = t.x; av[1] = t.y; av[2] = t.z; av[3] = t.w;
            } else av[0] = as_[s];
#pragma unroll
            for (int k = 0; k < H; k++) {
                float v = av[k] + add[k];
                v = v > 0.f ? v : 0.2f * v;
                ex[k] = expf(v);
                denl[k] += ex[k];
            }
        } else {
#pragma unroll
            for (int k = 0; k < H; k++) ex[k] = 0.f;
        }
        int cnt = min(32, r1 - base);
        for (int jb = 0; jb < cnt; jb += 2) {
            bool has1 = (jb + 1) < cnt;
            int s0 = __shfl_sync(0xFFFFFFFFu, s, jb);
            int s1 = __shfl_sync(0xFFFFFFFFu, s, jb + 1);
            if (!has1) s1 = s0;
            const float4* hp0 = (const float4*)(h + (size_t)s0 * (H * 128));
            const float4* hp1 = (const float4*)(h + (size_t)s1 * (H * 128));
            float4 hv0[H], hv1[H];
            float e0[H], e1[H];
#pragma unroll
            for (int k = 0; k < H; k++) {
                hv0[k] = hp0[k * 32 + lane];
                hv1[k] = hp1[k * 32 + lane];
                e0[k] = __shfl_sync(0xFFFFFFFFu, ex[k], jb);
                float t = __shfl_sync(0xFFFFFFFFu, ex[k], jb + 1);
                e1[k] = has1 ? t : 0.f;
            }
#pragma unroll
            for (int k = 0; k < H; k++) {
                acc[k][0] += e0[k] * hv0[k].x + e1[k] * hv1[k].x;
                acc[k][1] += e0[k] * hv0[k].y + e1[k] * hv1[k].y;
                acc[k][2] += e0[k] * hv0[k].z + e1[k] * hv1[k].z;
                acc[k][3] += e0[k] * hv0[k].w + e1[k] * hv1[k].w;
            }
        }
    }

    const float4* hpd = (const float4*)(h + (size_t)d * (H * 128));
#pragma unroll
    for (int k = 0; k < H; k++) {
        float v = asd[k] + add[k];
        v = v > 0.f ? v : 0.2f * v;
        float exs = expf(v);
        float4 hv = hpd[k * 32 + lane];
        acc[k][0] += exs * hv.x;
        acc[k][1] += exs * hv.y;
        acc[k][2] += exs * hv.z;
        acc[k][3] += exs * hv.w;
        float dk = denl[k];
#pragma unroll
        for (int o = 16; o; o >>= 1) dk += __shfl_xor_sync(0xFFFFFFFFu, dk, o);
        denl[k] = dk + exs;
    }

    float v0 = 0.f, v1 = 0.f, v2 = 0.f, v3 = 0.f;
#pragma unroll
    for (int k = 0; k < H; k++) {
        float r = 1.f / (denl[k] + 1e-16f);
        v0 += acc[k][0] * r;
        v1 += acc[k][1] * r;
        v2 += acc[k][2] * r;
        v3 += acc[k][3] * r;
    }
    if (H == 4) { v0 *= 0.25f; v1 *= 0.25f; v2 *= 0.25f; v3 *= 0.25f; }

    int c0 = lane * 4;
    float4 bz = *(const float4*)(bias + c0);
    v0 += bz.x; v1 += bz.y; v2 += bz.z; v3 += bz.w;

    if (DO_BN) {
        float4 gg = *(const float4*)(bg + c0);
        float4 bb4 = *(const float4*)(bb + c0);
        float4 mm = *(const float4*)(bm_ + c0);
        float4 vv = *(const float4*)(bv + c0);
        v0 = fmaxf(gg.x * (v0 - mm.x) * rsqrtf(vv.x + 1e-5f) + bb4.x, 0.f);
        v1 = fmaxf(gg.y * (v1 - mm.y) * rsqrtf(vv.y + 1e-5f) + bb4.y, 0.f);
        v2 = fmaxf(gg.z * (v2 - mm.z) * rsqrtf(vv.z + 1e-5f) + bb4.z, 0.f);
        v3 = fmaxf(gg.w * (v3 - mm.w) * rsqrtf(vv.w + 1e-5f) + bb4.w, 0.f);
    }

    // emit split-bf16 for the next GEMM
    __nv_bfloat16 h0 = __float2bfloat16(v0), h1 = __float2bfloat16(v1);
    __nv_bfloat16 h2 = __float2bfloat16(v2), h3 = __float2bfloat16(v3);
    __nv_bfloat16 l0 = __float2bfloat16(v0 - __bfloat162float(h0));
    __nv_bfloat16 l1 = __float2bfloat16(v1 - __bfloat162float(h1));
    __nv_bfloat16 l2 = __float2bfloat16(v2 - __bfloat162float(h2));
    __nv_bfloat16 l3 = __float2bfloat16(v3 - __bfloat162float(h3));
    *(uint2*)(outh + (size_t)d * 128 + c0) = make_uint2(pack_bf16(h0, h1), pack_bf16(h2, h3));
    *(uint2*)(outl + (size_t)d * 128 + c0) = make_uint2(pack_bf16(l0, l1), pack_bf16(l2, l3));
}

// ---------------- host-side orchestration -------------------------------------
static void launch_splitT(const float* W, __nv_bfloat16* hi, __nv_bfloat16* lo, int K, int N) {
    splitT_kernel<<<(K * N + 255) / 256, 256>>>(W, hi, lo, K, N);
}
static void launch_gemm(const __nv_bfloat16* Ah, const __nv_bfloat16* Al,
                        const __nv_bfloat16* Bh, const __nv_bfloat16* Bl,
                        const float* bias, float* C, __nv_bfloat16* Ch, __nv_bfloat16* Cl,
                        int M, int Ntot, int K, int act)
{
    static bool attr_set = false;
    size_t smem = (size_t)(128 + 128 + 64 + 64) * GLD * sizeof(__nv_bfloat16);
    if (!attr_set) {
        cudaFuncSetAttribute(mma_gemm_kernel, cudaFuncAttributeMaxDynamicSharedMemorySize,
                             (int)smem);
        attr_set = true;
    }
    dim3 grid(Ntot / 64, (M + 127) / 128);
    mma_gemm_kernel<<<grid, 256, smem>>>(Ah, Al, Bh, Bl, bias, C, Ch, Cl, M, Ntot, K, act);
}

extern "C" void kernel_launch(void* const* d_in, const int* in_sizes, int n_in,
                              void* d_out, int out_size)
{
    const float* x   = (const float*)d_in[0];
    const int*   ei  = (const int*)  d_in[1];
    const float* W1  = (const float*)d_in[2];
    const float* as1 = (const float*)d_in[3];
    const float* ad1 = (const float*)d_in[4];
    const float* b1  = (const float*)d_in[5];
    const float* W2  = (const float*)d_in[6];
    const float* as2 = (const float*)d_in[7];
    const float* ad2 = (const float*)d_in[8];
    const float* b2  = (const float*)d_in[9];
    const float* W3  = (const float*)d_in[10];
    const float* as3 = (const float*)d_in[11];
    const float* ad3 = (const float*)d_in[12];
    const float* b3  = (const float*)d_in[13];
    const float* bn1g = (const float*)d_in[14];
    const float* bn1b = (const float*)d_in[15];
    const float* bn1m = (const float*)d_in[16];
    const float* bn1v = (const float*)d_in[17];
    const float* bn2g = (const float*)d_in[18];
    const float* bn2b = (const float*)d_in[19];
    const float* bn2m = (const float*)d_in[20];
    const float* bn2v = (const float*)d_in[21];
    const float* l1w = (const float*)d_in[22];
    const float* l1b = (const float*)d_in[23];
    const float* l2w = (const float*)d_in[24];
    const float* l2b = (const float*)d_in[25];
    const float* l3w = (const float*)d_in[26];
    const float* l3b = (const float*)d_in[27];

    const int N = in_sizes[0] / 256;       // 20000
    const int E = in_sizes[1] / 2;         // 320000
    const int* src = ei;
    const int* dst = ei + E;

    float *h, *as_, *ad_;
    __nv_bfloat16 *ah, *al, *ah2, *al2, *bh, *bl;
    cudaGetSymbolAddress((void**)&h,   g_h);
    cudaGetSymbolAddress((void**)&as_, g_as);
    cudaGetSymbolAddress((void**)&ad_, g_ad);
    cudaGetSymbolAddress((void**)&ah,  g_ah);
    cudaGetSymbolAddress((void**)&al,  g_al);
    cudaGetSymbolAddress((void**)&ah2, g_ah2);
    cudaGetSymbolAddress((void**)&al2, g_al2);
    cudaGetSymbolAddress((void**)&bh,  g_bh);
    cudaGetSymbolAddress((void**)&bl,  g_bl);

    // ---- CSR build (dst identical for all 3 layers) ----
    zero_deg_kernel<<<(N + 255) / 256, 256>>>(N);
    hist_kernel<<<(E + 255) / 256, 256>>>(dst, E);
    scan_kernel<<<1, 1024>>>(N);
    scatter_kernel<<<(E + 255) / 256, 256>>>(src, dst, E);

    int agg_blocks = (N * 32 + 255) / 256;

    // ---- GAT layer 1 (heads=4, mean) + BN1 + relu ----
    split_kernel<<<(N * 256 + 255) / 256, 256>>>(x, ah, al, N * 256);
    launch_splitT(W1, bh, bl, 256, 512);
    launch_gemm(ah, al, bh, bl, nullptr, h, nullptr, nullptr, N, 512, 256, 0);
    alpha_kernel<<<(N * 4 * 32 + 255) / 256, 256>>>(h, as1, ad1, as_, ad_, N, 4);
    gat_agg_kernel<4, true><<<agg_blocks, 256>>>(h, as_, ad_, b1, bn1g, bn1b, bn1m, bn1v, ah2, al2, N);

    // ---- GAT layer 2 (heads=4, mean) + BN2 + relu ----
    launch_splitT(W2, bh, bl, 128, 512);
    launch_gemm(ah2, al2, bh, bl, nullptr, h, nullptr, nullptr, N, 512, 128, 0);
    alpha_kernel<<<(N * 4 * 32 + 255) / 256, 256>>>(h, as2, ad2, as_, ad_, N, 4);
    gat_agg_kernel<4, true><<<agg_blocks, 256>>>(h, as_, ad_, b2, bn2g, bn2b, bn2m, bn2v, ah, al, N);

    // ---- GAT layer 3 (heads=1, concat) ----
    launch_splitT(W3, bh, bl, 128, 128);
    launch_gemm(ah, al, bh, bl, nullptr, h, nullptr, nullptr, N, 128, 128, 0);
    alpha_kernel<<<(N * 32 + 255) / 256, 256>>>(h, as3, ad3, as_, ad_, N, 1);
    gat_agg_kernel<1, false><<<agg_blocks, 256>>>(h, as_, ad_, b3, nullptr, nullptr, nullptr, nullptr, ah2, al2, N);

    // ---- classifier MLP (split-bf16 flows through epilogues) ----
    launch_splitT(l1w, bh, bl, 128, 128);
    launch_gemm(ah2, al2, bh, bl, l1b, nullptr, ah, al, N, 128, 128, 1);      // relu

    launch_splitT(l2w, bh, bl, 128, 64);
    launch_gemm(ah, al, bh, bl, l2b, nullptr, ah2, al2, N, 64, 128, 1);       // relu

    launch_splitT(l3w, bh, bl, 64, 64);
    launch_gemm(ah2, al2, bh, bl, l3b, (float*)d_out, nullptr, nullptr, N, 64, 64, 2);  // sigmoid
}

// round 15
// speedup vs baseline: 1.3987x; 1.3987x over previous
#include <cuda_runtime.h>
#include <cuda_bf16.h>
#include <math.h>
#include <stdint.h>

#define N_NODES 20000
#define E_MAX   320000

// ---------------- device scratch ----------------------------------------------
__device__ float g_h  [N_NODES * 512];
__device__ float g_as [N_NODES * 4];
__device__ float g_ad [N_NODES * 4];
__device__ int   g_deg[N_NODES];
__device__ int   g_off[N_NODES + 1];
__device__ int   g_cur[N_NODES];
__device__ int   g_csr[E_MAX];
__device__ __nv_bfloat16 g_ah [N_NODES * 256];  // split activations ping (hi)
__device__ __nv_bfloat16 g_al [N_NODES * 256];  // split activations ping (lo)
__device__ __nv_bfloat16 g_ah2[N_NODES * 128];  // split activations pong (hi)
__device__ __nv_bfloat16 g_al2[N_NODES * 128];  // split activations pong (lo)
__device__ __nv_bfloat16 g_bh[512 * 256];       // split transposed weights (hi)
__device__ __nv_bfloat16 g_bl[512 * 256];       // split transposed weights (lo)

// ---------------- warp MMA helpers (baseline PTX: ldmatrix + mma.sync) --------
__device__ __forceinline__ uint32_t smem_u32(const void* p) {
    uint32_t a;
    asm("{ .reg .u64 t; cvta.to.shared.u64 t, %1; cvt.u32.u64 %0, t; }" : "=r"(a) : "l"(p));
    return a;
}
__device__ __forceinline__ void ldsm_x4(uint32_t* d, uint32_t addr) {
    asm volatile("ldmatrix.sync.aligned.m8n8.x4.shared.b16 {%0,%1,%2,%3}, [%4];"
                 : "=r"(d[0]), "=r"(d[1]), "=r"(d[2]), "=r"(d[3]) : "r"(addr));
}
__device__ __forceinline__ void ldsm_x2(uint32_t* d, uint32_t addr) {
    asm volatile("ldmatrix.sync.aligned.m8n8.x2.shared.b16 {%0,%1}, [%2];"
                 : "=r"(d[0]), "=r"(d[1]) : "r"(addr));
}
__device__ __forceinline__ void mma_bf16(float* c, const uint32_t* a, const uint32_t* b) {
    asm volatile("mma.sync.aligned.m16n8k16.row.col.f32.bf16.bf16.f32 "
                 "{%0,%1,%2,%3}, {%4,%5,%6,%7}, {%8,%9}, {%0,%1,%2,%3};"
                 : "+f"(c[0]), "+f"(c[1]), "+f"(c[2]), "+f"(c[3])
                 : "r"(a[0]), "r"(a[1]), "r"(a[2]), "r"(a[3]), "r"(b[0]), "r"(b[1]));
}
__device__ __forceinline__ uint32_t pack_bf16(__nv_bfloat16 a, __nv_bfloat16 b) {
    __nv_bfloat162 t = __halves2bfloat162(a, b);
    return *reinterpret_cast<uint32_t*>(&t);
}

// ---------------- CSR build ----------------------------------------------------
__global__ void zero_deg_kernel(int N) {
    int i = blockIdx.x * blockDim.x + threadIdx.x;
    if (i < N) g_deg[i] = 0;
}
__global__ void hist_kernel(const int* __restrict__ dst, int E) {
    int i = blockIdx.x * blockDim.x + threadIdx.x;
    if (i < E) atomicAdd(&g_deg[dst[i]], 1);
}
__global__ void scan_kernel(int N) {
    __shared__ int sh[1024];
    int tid = threadIdx.x;
    int per = (N + 1023) >> 10;
    int base = tid * per;
    int sum = 0;
    for (int i = 0; i < per; i++) { int idx = base + i; if (idx < N) sum += g_deg[idx]; }
    sh[tid] = sum;
    __syncthreads();
    for (int off = 1; off < 1024; off <<= 1) {
        int v = (tid >= off) ? sh[tid - off] : 0;
        __syncthreads();
        sh[tid] += v;
        __syncthreads();
    }
    int run = tid ? sh[tid - 1] : 0;
    for (int i = 0; i < per; i++) {
        int idx = base + i;
        if (idx < N) { g_off[idx] = run; g_cur[idx] = run; run += g_deg[idx]; }
    }
    if (tid == 1023) g_off[N] = sh[1023];
}
__global__ void scatter_kernel(const int* __restrict__ src, const int* __restrict__ dst, int E) {
    int i = blockIdx.x * blockDim.x + threadIdx.x;
    if (i < E) {
        int p = atomicAdd(&g_cur[dst[i]], 1);
        g_csr[p] = src[i];
    }
}

// ---------------- split-bf16 conversions ---------------------------------------
__global__ void split_kernel(const float* __restrict__ in, __nv_bfloat16* __restrict__ hi,
                             __nv_bfloat16* __restrict__ lo, int n)
{
    int i = blockIdx.x * blockDim.x + threadIdx.x;
    if (i >= n) return;
    float x = in[i];
    __nv_bfloat16 h = __float2bfloat16(x);
    hi[i] = h;
    lo[i] = __float2bfloat16(x - __bfloat162float(h));
}
// W [K,N] row-major -> Wt hi/lo [N,K]
__global__ void splitT_kernel(const float* __restrict__ W, __nv_bfloat16* __restrict__ hi,
                              __nv_bfloat16* __restrict__ lo, int K, int N)
{
    int i = blockIdx.x * blockDim.x + threadIdx.x;
    if (i >= K * N) return;
    int n = i / K, k = i - n * K;
    float x = W[(size_t)k * N + n];
    __nv_bfloat16 h = __float2bfloat16(x);
    hi[i] = h;
    lo[i] = __float2bfloat16(x - __bfloat162float(h));
}

// ---------------- split-bf16 tensor-core GEMM (mma.sync) -----------------------
// C[M,Ntot] = (Ah+Al)[M,K] @ (Bh+Bl)^T   (B stored [Ntot,K] K-major)
// Block tile 128Mx64Nx64K, 8 warps (4x2), warp tile 32x32.
// Output: f32 C (if non-null) and/or split-bf16 Ch/Cl (if non-null).
// act: 0 none, 1 relu, 2 sigmoid
#define GLD 72
__global__ __launch_bounds__(256)
void mma_gemm_kernel(const __nv_bfloat16* __restrict__ Ah, const __nv_bfloat16* __restrict__ Al,
                     const __nv_bfloat16* __restrict__ Bh, const __nv_bfloat16* __restrict__ Bl,
                     const float* __restrict__ bias, float* __restrict__ C,
                     __nv_bfloat16* __restrict__ Ch, __nv_bfloat16* __restrict__ Cl,
                     int M, int Ntot, int K, int act)
{
    extern __shared__ __nv_bfloat16 sm[];
    __nv_bfloat16* sAh = sm;
    __nv_bfloat16* sAl = sAh + 128 * GLD;
    __nv_bfloat16* sBh = sAl + 128 * GLD;
    __nv_bfloat16* sBl = sBh + 64 * GLD;

    int tid = threadIdx.x, lane = tid & 31, warp = tid >> 5;
    int wm = warp >> 1, wn = warp & 1;
    int bm = blockIdx.y * 128, bn = blockIdx.x * 64;

    uint32_t aAh = smem_u32(sAh), aAl = smem_u32(sAl);
    uint32_t aBh = smem_u32(sBh), aBl = smem_u32(sBl);

    float acc[2][4][4];
#pragma unroll
    for (int mt = 0; mt < 2; mt++)
#pragma unroll
        for (int nt = 0; nt < 4; nt++)
#pragma unroll
            for (int q = 0; q < 4; q++) acc[mt][nt][q] = 0.f;

    for (int kc = 0; kc < K; kc += 64) {
        for (int i = tid; i < 2048; i += 256) {
            int row = i >> 4, seg = (i & 15) << 2;
            int m = bm + row, k = kc + seg;
            uint2 hv = make_uint2(0u, 0u), lv = make_uint2(0u, 0u);
            if (m < M) {
                hv = *(const uint2*)(Ah + (size_t)m * K + k);
                lv = *(const uint2*)(Al + (size_t)m * K + k);
            }
            *(uint2*)&sAh[row * GLD + seg] = hv;
            *(uint2*)&sAl[row * GLD + seg] = lv;
        }
        for (int i = tid; i < 1024; i += 256) {
            int row = i >> 4, seg = (i & 15) << 2;
            int n = bn + row, k = kc + seg;
            *(uint2*)&sBh[row * GLD + seg] = *(const uint2*)(Bh + (size_t)n * K + k);
            *(uint2*)&sBl[row * GLD + seg] = *(const uint2*)(Bl + (size_t)n * K + k);
        }
        __syncthreads();

#pragma unroll
        for (int ks = 0; ks < 64; ks += 16) {
            uint32_t ah[2][4], al[2][4];
            int ar = lane & 15, ac = (lane >> 4) << 3;
#pragma unroll
            for (int mt = 0; mt < 2; mt++) {
                uint32_t off = (uint32_t)((wm * 32 + mt * 16 + ar) * GLD + ks + ac) * 2;
                ldsm_x4(ah[mt], aAh + off);
                ldsm_x4(al[mt], aAl + off);
            }
            uint32_t bh[4][2], bl[4][2];
            int br = lane & 7, bc = ((lane >> 3) & 1) << 3;
#pragma unroll
            for (int nt = 0; nt < 4; nt++) {
                uint32_t off = (uint32_t)((wn * 32 + nt * 8 + br) * GLD + ks + bc) * 2;
                ldsm_x2(bh[nt], aBh + off);
                ldsm_x2(bl[nt], aBl + off);
            }
#pragma unroll
            for (int mt = 0; mt < 2; mt++)
#pragma unroll
                for (int nt = 0; nt < 4; nt++) {
                    mma_bf16(acc[mt][nt], ah[mt], bh[nt]);
                    mma_bf16(acc[mt][nt], ah[mt], bl[nt]);
                    mma_bf16(acc[mt][nt], al[mt], bh[nt]);
                }
        }
        __syncthreads();
    }

    int rb = bm + wm * 32 + (lane >> 2);
    int cb = bn + wn * 32 + ((lane & 3) << 1);
#pragma unroll
    for (int mt = 0; mt < 2; mt++) {
        int r = rb + mt * 16;
#pragma unroll
        for (int nt = 0; nt < 4; nt++) {
            int c = cb + nt * 8;
            float bx = bias ? bias[c] : 0.f, by = bias ? bias[c + 1] : 0.f;
#pragma unroll
            for (int half = 0; half < 2; half++) {
                int rr = r + half * 8;
                if (rr >= M) continue;
                float v0 = acc[mt][nt][half * 2 + 0] + bx;
                float v1 = acc[mt][nt][half * 2 + 1] + by;
                if (act == 1)      { v0 = fmaxf(v0, 0.f); v1 = fmaxf(v1, 0.f); }
                else if (act == 2) { v0 = 1.f / (1.f + expf(-v0)); v1 = 1.f / (1.f + expf(-v1)); }
                if (C) *(float2*)(C + (size_t)rr * Ntot + c) = make_float2(v0, v1);
                if (Ch) {
                    __nv_bfloat16 h0 = __float2bfloat16(v0), h1 = __float2bfloat16(v1);
                    __nv_bfloat16 l0 = __float2bfloat16(v0 - __bfloat162float(h0));
                    __nv_bfloat16 l1 = __float2bfloat16(v1 - __bfloat162float(h1));
                    *(uint32_t*)(Ch + (size_t)rr * Ntot + c) = pack_bf16(h0, h1);
                    *(uint32_t*)(Cl + (size_t)rr * Ntot + c) = pack_bf16(l0, l1);
                }
            }
        }
    }
}

// ---------------- attention coefficient precompute ----------------------------
__global__ void alpha_kernel(const float* __restrict__ h, const float* __restrict__ a_src,
                             const float* __restrict__ a_dst, float* __restrict__ as_,
                             float* __restrict__ ad_, int N, int H)
{
    int gw = (blockIdx.x * blockDim.x + threadIdx.x) >> 5;
    int lane = threadIdx.x & 31;
    if (gw >= N * H) return;
    int n = gw / H, hh = gw - n * H;
    const float4* hp = (const float4*)(h + ((size_t)n * H + hh) * 128);
    const float4* sp = (const float4*)(a_src + hh * 128);
    const float4* dp = (const float4*)(a_dst + hh * 128);
    float4 v = hp[lane], sv = sp[lane], dv = dp[lane];
    float s = v.x * sv.x + v.y * sv.y + v.z * sv.z + v.w * sv.w;
    float d = v.x * dv.x + v.y * dv.y + v.z * dv.z + v.w * dv.w;
#pragma unroll
    for (int o = 16; o; o >>= 1) {
        s += __shfl_xor_sync(0xFFFFFFFFu, s, o);
        d += __shfl_xor_sync(0xFFFFFFFFu, d, o);
    }
    if (lane == 0) { as_[n * H + hh] = s; ad_[n * H + hh] = d; }
}

// ---------------- fused GAT aggregation (one warp per dst node) ----------------
// Round-11 inner loop (single-edge gather; low reg pressure). Epilogue emits
// split-bf16 (hi/lo) directly for the next GEMM's A operand.
template<int H, bool DO_BN>
__global__ void gat_agg_kernel(const float* __restrict__ h,
                               const float* __restrict__ as_, const float* __restrict__ ad_,
                               const float* __restrict__ bias,
                               const float* __restrict__ bg, const float* __restrict__ bb,
                               const float* __restrict__ bm_, const float* __restrict__ bv,
                               __nv_bfloat16* __restrict__ outh,
                               __nv_bfloat16* __restrict__ outl, int N)
{
    int d = (blockIdx.x * blockDim.x + threadIdx.x) >> 5;
    int lane = threadIdx.x & 31;
    if (d >= N) return;

    float asd[H], add[H];
    if (H == 4) {
        float4 t = ((const float4*)as_)[d];
        asd[0] = t.x; asd[1] = t.y; asd[2] = t.z; asd[3] = t.w;
        t = ((const float4*)ad_)[d];
        add[0] = t.x; add[1] = t.y; add[2] = t.z; add[3] = t.w;
    } else {
        asd[0] = as_[d]; add[0] = ad_[d];
    }

    float acc[H][4];
    float denl[H];
#pragma unroll
    for (int k = 0; k < H; k++) {
        denl[k] = 0.f;
#pragma unroll
        for (int c = 0; c < 4; c++) acc[k][c] = 0.f;
    }

    int r0 = g_off[d], r1 = g_off[d + 1];
    for (int base = r0; base < r1; base += 32) {
        int e = base + lane;
        int s = 0;
        float ex[H];
        if (e < r1) {
            s = g_csr[e];
            float av[H];
            if (H == 4) {
                float4 t = ((const float4*)as_)[s];
                av[0] = t.x; av[1] = t.y; av[2] = t.z; av[3] = t.w;
            } else av[0] = as_[s];
#pragma unroll
            for (int k = 0; k < H; k++) {
                float v = av[k] + add[k];
                v = v > 0.f ? v : 0.2f * v;
                ex[k] = expf(v);
                denl[k] += ex[k];
            }
        } else {
#pragma unroll
            for (int k = 0; k < H; k++) ex[k] = 0.f;
        }
        int cnt = min(32, r1 - base);
        for (int j = 0; j < cnt; j++) {
            int sj = __shfl_sync(0xFFFFFFFFu, s, j);
            const float4* hp = (const float4*)(h + (size_t)sj * (H * 128));
#pragma unroll
            for (int k = 0; k < H; k++) {
                float exj = __shfl_sync(0xFFFFFFFFu, ex[k], j);
                float4 hv = hp[k * 32 + lane];
                acc[k][0] += exj * hv.x;
                acc[k][1] += exj * hv.y;
                acc[k][2] += exj * hv.z;
                acc[k][3] += exj * hv.w;
            }
        }
    }

    const float4* hpd = (const float4*)(h + (size_t)d * (H * 128));
#pragma unroll
    for (int k = 0; k < H; k++) {
        float v = asd[k] + add[k];
        v = v > 0.f ? v : 0.2f * v;
        float exs = expf(v);
        float4 hv = hpd[k * 32 + lane];
        acc[k][0] += exs * hv.x;
        acc[k][1] += exs * hv.y;
        acc[k][2] += exs * hv.z;
        acc[k][3] += exs * hv.w;
        float dk = denl[k];
#pragma unroll
        for (int o = 16; o; o >>= 1) dk += __shfl_xor_sync(0xFFFFFFFFu, dk, o);
        denl[k] = dk + exs;
    }

    float v0 = 0.f, v1 = 0.f, v2 = 0.f, v3 = 0.f;
#pragma unroll
    for (int k = 0; k < H; k++) {
        float r = 1.f / (denl[k] + 1e-16f);
        v0 += acc[k][0] * r;
        v1 += acc[k][1] * r;
        v2 += acc[k][2] * r;
        v3 += acc[k][3] * r;
    }
    if (H == 4) { v0 *= 0.25f; v1 *= 0.25f; v2 *= 0.25f; v3 *= 0.25f; }

    int c0 = lane * 4;
    float4 bz = *(const float4*)(bias + c0);
    v0 += bz.x; v1 += bz.y; v2 += bz.z; v3 += bz.w;

    if (DO_BN) {
        float4 gg = *(const float4*)(bg + c0);
        float4 bb4 = *(const float4*)(bb + c0);
        float4 mm = *(const float4*)(bm_ + c0);
        float4 vv = *(const float4*)(bv + c0);
        v0 = fmaxf(gg.x * (v0 - mm.x) * rsqrtf(vv.x + 1e-5f) + bb4.x, 0.f);
        v1 = fmaxf(gg.y * (v1 - mm.y) * rsqrtf(vv.y + 1e-5f) + bb4.y, 0.f);
        v2 = fmaxf(gg.z * (v2 - mm.z) * rsqrtf(vv.z + 1e-5f) + bb4.z, 0.f);
        v3 = fmaxf(gg.w * (v3 - mm.w) * rsqrtf(vv.w + 1e-5f) + bb4.w, 0.f);
    }

    // emit split-bf16 for the next GEMM
    __nv_bfloat16 h0 = __float2bfloat16(v0), h1 = __float2bfloat16(v1);
    __nv_bfloat16 h2 = __float2bfloat16(v2), h3 = __float2bfloat16(v3);
    __nv_bfloat16 l0 = __float2bfloat16(v0 - __bfloat162float(h0));
    __nv_bfloat16 l1 = __float2bfloat16(v1 - __bfloat162float(h1));
    __nv_bfloat16 l2 = __float2bfloat16(v2 - __bfloat162float(h2));
    __nv_bfloat16 l3 = __float2bfloat16(v3 - __bfloat162float(h3));
    *(uint2*)(outh + (size_t)d * 128 + c0) = make_uint2(pack_bf16(h0, h1), pack_bf16(h2, h3));
    *(uint2*)(outl + (size_t)d * 128 + c0) = make_uint2(pack_bf16(l0, l1), pack_bf16(l2, l3));
}

// ---------------- host-side orchestration -------------------------------------
static void launch_splitT(const float* W, __nv_bfloat16* hi, __nv_bfloat16* lo, int K, int N) {
    splitT_kernel<<<(K * N + 255) / 256, 256>>>(W, hi, lo, K, N);
}
static void launch_gemm(const __nv_bfloat16* Ah, const __nv_bfloat16* Al,
                        const __nv_bfloat16* Bh, const __nv_bfloat16* Bl,
                        const float* bias, float* C, __nv_bfloat16* Ch, __nv_bfloat16* Cl,
                        int M, int Ntot, int K, int act)
{
    static bool attr_set = false;
    size_t smem = (size_t)(128 + 128 + 64 + 64) * GLD * sizeof(__nv_bfloat16);
    if (!attr_set) {
        cudaFuncSetAttribute(mma_gemm_kernel, cudaFuncAttributeMaxDynamicSharedMemorySize,
                             (int)smem);
        attr_set = true;
    }
    dim3 grid(Ntot / 64, (M + 127) / 128);
    mma_gemm_kernel<<<grid, 256, smem>>>(Ah, Al, Bh, Bl, bias, C, Ch, Cl, M, Ntot, K, act);
}

extern "C" void kernel_launch(void* const* d_in, const int* in_sizes, int n_in,
                              void* d_out, int out_size)
{
    const float* x   = (const float*)d_in[0];
    const int*   ei  = (const int*)  d_in[1];
    const float* W1  = (const float*)d_in[2];
    const float* as1 = (const float*)d_in[3];
    const float* ad1 = (const float*)d_in[4];
    const float* b1  = (const float*)d_in[5];
    const float* W2  = (const float*)d_in[6];
    const float* as2 = (const float*)d_in[7];
    const float* ad2 = (const float*)d_in[8];
    const float* b2  = (const float*)d_in[9];
    const float* W3  = (const float*)d_in[10];
    const float* as3 = (const float*)d_in[11];
    const float* ad3 = (const float*)d_in[12];
    const float* b3  = (const float*)d_in[13];
    const float* bn1g = (const float*)d_in[14];
    const float* bn1b = (const float*)d_in[15];
    const float* bn1m = (const float*)d_in[16];
    const float* bn1v = (const float*)d_in[17];
    const float* bn2g = (const float*)d_in[18];
    const float* bn2b = (const float*)d_in[19];
    const float* bn2m = (const float*)d_in[20];
    const float* bn2v = (const float*)d_in[21];
    const float* l1w = (const float*)d_in[22];
    const float* l1b = (const float*)d_in[23];
    const float* l2w = (const float*)d_in[24];
    const float* l2b = (const float*)d_in[25];
    const float* l3w = (const float*)d_in[26];
    const float* l3b = (const float*)d_in[27];

    const int N = in_sizes[0] / 256;       // 20000
    const int E = in_sizes[1] / 2;         // 320000
    const int* src = ei;
    const int* dst = ei + E;

    float *h, *as_, *ad_;
    __nv_bfloat16 *ah, *al, *ah2, *al2, *bh, *bl;
    cudaGetSymbolAddress((void**)&h,   g_h);
    cudaGetSymbolAddress((void**)&as_, g_as);
    cudaGetSymbolAddress((void**)&ad_, g_ad);
    cudaGetSymbolAddress((void**)&ah,  g_ah);
    cudaGetSymbolAddress((void**)&al,  g_al);
    cudaGetSymbolAddress((void**)&ah2, g_ah2);
    cudaGetSymbolAddress((void**)&al2, g_al2);
    cudaGetSymbolAddress((void**)&bh,  g_bh);
    cudaGetSymbolAddress((void**)&bl,  g_bl);

    // ---- CSR build (dst identical for all 3 layers) ----
    zero_deg_kernel<<<(N + 255) / 256, 256>>>(N);
    hist_kernel<<<(E + 255) / 256, 256>>>(dst, E);
    scan_kernel<<<1, 1024>>>(N);
    scatter_kernel<<<(E + 255) / 256, 256>>>(src, dst, E);

    int agg_blocks = (N * 32 + 255) / 256;

    // ---- GAT layer 1 (heads=4, mean) + BN1 + relu ----
    split_kernel<<<(N * 256 + 255) / 256, 256>>>(x, ah, al, N * 256);
    launch_splitT(W1, bh, bl, 256, 512);
    launch_gemm(ah, al, bh, bl, nullptr, h, nullptr, nullptr, N, 512, 256, 0);
    alpha_kernel<<<(N * 4 * 32 + 255) / 256, 256>>>(h, as1, ad1, as_, ad_, N, 4);
    gat_agg_kernel<4, true><<<agg_blocks, 256>>>(h, as_, ad_, b1, bn1g, bn1b, bn1m, bn1v, ah2, al2, N);

    // ---- GAT layer 2 (heads=4, mean) + BN2 + relu ----
    launch_splitT(W2, bh, bl, 128, 512);
    launch_gemm(ah2, al2, bh, bl, nullptr, h, nullptr, nullptr, N, 512, 128, 0);
    alpha_kernel<<<(N * 4 * 32 + 255) / 256, 256>>>(h, as2, ad2, as_, ad_, N, 4);
    gat_agg_kernel<4, true><<<agg_blocks, 256>>>(h, as_, ad_, b2, bn2g, bn2b, bn2m, bn2v, ah, al, N);

    // ---- GAT layer 3 (heads=1, concat) ----
    launch_splitT(W3, bh, bl, 128, 128);
    launch_gemm(ah, al, bh, bl, nullptr, h, nullptr, nullptr, N, 128, 128, 0);
    alpha_kernel<<<(N * 32 + 255) / 256, 256>>>(h, as3, ad3, as_, ad_, N, 1);
    gat_agg_kernel<1, false><<<agg_blocks, 256>>>(h, as_, ad_, b3, nullptr, nullptr, nullptr, nullptr, ah2, al2, N);

    // ---- classifier MLP (split-bf16 flows through epilogues) ----
    launch_splitT(l1w, bh, bl, 128, 128);
    launch_gemm(ah2, al2, bh, bl, l1b, nullptr, ah, al, N, 128, 128, 1);      // relu

    launch_splitT(l2w, bh, bl, 128, 64);
    launch_gemm(ah, al, bh, bl, l2b, nullptr, ah2, al2, N, 64, 128, 1);       // relu

    launch_splitT(l3w, bh, bl, 64, 64);
    launch_gemm(ah2, al2, bh, bl, l3b, (float*)d_out, nullptr, nullptr, N, 64, 64, 2);  // sigmoid
}

// round 16
// speedup vs baseline: 1.4439x; 1.0323x over previous
#include <cuda_runtime.h>
#include <cuda_bf16.h>
#include <cuda_fp16.h>
#include <math.h>
#include <stdint.h>

#define N_NODES 20000
#define E_MAX   320000

// ---------------- device scratch ----------------------------------------------
__device__ float  g_h  [N_NODES * 512];          // f32 transformed features (alpha)
__device__ __half g_h16[N_NODES * 512];          // fp16 mirror (gather path)
__device__ float  g_as [N_NODES * 4];
__device__ float  g_ad [N_NODES * 4];
__device__ int    g_deg[N_NODES];
__device__ int    g_off[N_NODES + 1];
__device__ int    g_cur[N_NODES];
__device__ int    g_csr[E_MAX];
__device__ __nv_bfloat16 g_ah [N_NODES * 256];   // split activations ping (hi)
__device__ __nv_bfloat16 g_al [N_NODES * 256];   // split activations ping (lo)
__device__ __nv_bfloat16 g_ah2[N_NODES * 128];   // split activations pong (hi)
__device__ __nv_bfloat16 g_al2[N_NODES * 128];   // split activations pong (lo)
__device__ __nv_bfloat16 g_bh[242000];           // all split transposed weights (hi)
__device__ __nv_bfloat16 g_bl[242000];           // all split transposed weights (lo)

// weight segment offsets in g_bh/g_bl
#define OFF_W1 0
#define OFF_W2 131072
#define OFF_W3 196608
#define OFF_L1 212992
#define OFF_L2 229376
#define OFF_L3 237568

// ---------------- warp MMA helpers (baseline PTX: ldmatrix + mma.sync) --------
__device__ __forceinline__ uint32_t smem_u32(const void* p) {
    uint32_t a;
    asm("{ .reg .u64 t; cvta.to.shared.u64 t, %1; cvt.u32.u64 %0, t; }" : "=r"(a) : "l"(p));
    return a;
}
__device__ __forceinline__ void ldsm_x4(uint32_t* d, uint32_t addr) {
    asm volatile("ldmatrix.sync.aligned.m8n8.x4.shared.b16 {%0,%1,%2,%3}, [%4];"
                 : "=r"(d[0]), "=r"(d[1]), "=r"(d[2]), "=r"(d[3]) : "r"(addr));
}
__device__ __forceinline__ void ldsm_x2(uint32_t* d, uint32_t addr) {
    asm volatile("ldmatrix.sync.aligned.m8n8.x2.shared.b16 {%0,%1}, [%2];"
                 : "=r"(d[0]), "=r"(d[1]) : "r"(addr));
}
__device__ __forceinline__ void mma_bf16(float* c, const uint32_t* a, const uint32_t* b) {
    asm volatile("mma.sync.aligned.m16n8k16.row.col.f32.bf16.bf16.f32 "
                 "{%0,%1,%2,%3}, {%4,%5,%6,%7}, {%8,%9}, {%0,%1,%2,%3};"
                 : "+f"(c[0]), "+f"(c[1]), "+f"(c[2]), "+f"(c[3])
                 : "r"(a[0]), "r"(a[1]), "r"(a[2]), "r"(a[3]), "r"(b[0]), "r"(b[1]));
}
__device__ __forceinline__ uint32_t pack_bf16(__nv_bfloat16 a, __nv_bfloat16 b) {
    __nv_bfloat162 t = __halves2bfloat162(a, b);
    return *reinterpret_cast<uint32_t*>(&t);
}

// ---------------- CSR build ----------------------------------------------------
__global__ void zero_deg_kernel(int N) {
    int i = blockIdx.x * blockDim.x + threadIdx.x;
    if (i < N) g_deg[i] = 0;
}
__global__ void hist_kernel(const int* __restrict__ dst, int E) {
    int i = blockIdx.x * blockDim.x + threadIdx.x;
    if (i < E) atomicAdd(&g_deg[dst[i]], 1);
}
__global__ void scan_kernel(int N) {
    __shared__ int sh[1024];
    int tid = threadIdx.x;
    int per = (N + 1023) >> 10;
    int base = tid * per;
    int sum = 0;
    for (int i = 0; i < per; i++) { int idx = base + i; if (idx < N) sum += g_deg[idx]; }
    sh[tid] = sum;
    __syncthreads();
    for (int off = 1; off < 1024; off <<= 1) {
        int v = (tid >= off) ? sh[tid - off] : 0;
        __syncthreads();
        sh[tid] += v;
        __syncthreads();
    }
    int run = tid ? sh[tid - 1] : 0;
    for (int i = 0; i < per; i++) {
        int idx = base + i;
        if (idx < N) { g_off[idx] = run; g_cur[idx] = run; run += g_deg[idx]; }
    }
    if (tid == 1023) g_off[N] = sh[1023];
}
__global__ void scatter_kernel(const int* __restrict__ src, const int* __restrict__ dst, int E) {
    int i = blockIdx.x * blockDim.x + threadIdx.x;
    if (i < E) {
        int p = atomicAdd(&g_cur[dst[i]], 1);
        g_csr[p] = src[i];
    }
}

// ---------------- split-bf16 conversions ---------------------------------------
__global__ void split_kernel(const float* __restrict__ in, __nv_bfloat16* __restrict__ hi,
                             __nv_bfloat16* __restrict__ lo, int n)
{
    int i = blockIdx.x * blockDim.x + threadIdx.x;
    if (i >= n) return;
    float x = in[i];
    __nv_bfloat16 h = __float2bfloat16(x);
    hi[i] = h;
    lo[i] = __float2bfloat16(x - __bfloat162float(h));
}

// One kernel splits + transposes ALL weight matrices into g_bh/g_bl segments.
__global__ void splitT_all_kernel(const float* __restrict__ W1, const float* __restrict__ W2,
                                  const float* __restrict__ W3, const float* __restrict__ L1,
                                  const float* __restrict__ L2, const float* __restrict__ L3)
{
    int i = blockIdx.x * blockDim.x + threadIdx.x;
    const float* W; int K, off, li;
    if      (i < OFF_W2)  { W = W1; K = 256; off = OFF_W1; li = i - OFF_W1; }
    else if (i < OFF_W3)  { W = W2; K = 128; off = OFF_W2; li = i - OFF_W2; }
    else if (i < OFF_L1)  { W = W3; K = 128; off = OFF_W3; li = i - OFF_W3; }
    else if (i < OFF_L2)  { W = L1; K = 128; off = OFF_L1; li = i - OFF_L1; }
    else if (i < OFF_L3)  { W = L2; K = 128; off = OFF_L2; li = i - OFF_L2; }
    else if (i < OFF_L3 + 4096) { W = L3; K = 64; off = OFF_L3; li = i - OFF_L3; }
    else return;
    int n = li / K, k = li - n * K;
    int N = 0;
    // N (output dim) per matrix
    if (off == OFF_W1) N = 512; else if (off == OFF_W2) N = 512; else if (off == OFF_W3) N = 128;
    else if (off == OFF_L1) N = 128; else if (off == OFF_L2) N = 64; else N = 64;
    float x = W[(size_t)k * N + n];
    __nv_bfloat16 h = __float2bfloat16(x);
    g_bh[off + li] = h;
    g_bl[off + li] = __float2bfloat16(x - __bfloat162float(h));
}

// ---------------- split-bf16 tensor-core GEMM (mma.sync) -----------------------
// C f32 (optional), H16 fp16 mirror (optional), Ch/Cl split-bf16 (optional).
// act: 0 none, 1 relu, 2 sigmoid
#define GLD 72
__global__ __launch_bounds__(256)
void mma_gemm_kernel(const __nv_bfloat16* __restrict__ Ah, const __nv_bfloat16* __restrict__ Al,
                     const __nv_bfloat16* __restrict__ Bh, const __nv_bfloat16* __restrict__ Bl,
                     const float* __restrict__ bias, float* __restrict__ C,
                     __half* __restrict__ H16,
                     __nv_bfloat16* __restrict__ Ch, __nv_bfloat16* __restrict__ Cl,
                     int M, int Ntot, int K, int act)
{
    extern __shared__ __nv_bfloat16 sm[];
    __nv_bfloat16* sAh = sm;
    __nv_bfloat16* sAl = sAh + 128 * GLD;
    __nv_bfloat16* sBh = sAl + 128 * GLD;
    __nv_bfloat16* sBl = sBh + 64 * GLD;

    int tid = threadIdx.x, lane = tid & 31, warp = tid >> 5;
    int wm = warp >> 1, wn = warp & 1;
    int bm = blockIdx.y * 128, bn = blockIdx.x * 64;

    uint32_t aAh = smem_u32(sAh), aAl = smem_u32(sAl);
    uint32_t aBh = smem_u32(sBh), aBl = smem_u32(sBl);

    float acc[2][4][4];
#pragma unroll
    for (int mt = 0; mt < 2; mt++)
#pragma unroll
        for (int nt = 0; nt < 4; nt++)
#pragma unroll
            for (int q = 0; q < 4; q++) acc[mt][nt][q] = 0.f;

    for (int kc = 0; kc < K; kc += 64) {
        for (int i = tid; i < 2048; i += 256) {
            int row = i >> 4, seg = (i & 15) << 2;
            int m = bm + row, k = kc + seg;
            uint2 hv = make_uint2(0u, 0u), lv = make_uint2(0u, 0u);
            if (m < M) {
                hv = *(const uint2*)(Ah + (size_t)m * K + k);
                lv = *(const uint2*)(Al + (size_t)m * K + k);
            }
            *(uint2*)&sAh[row * GLD + seg] = hv;
            *(uint2*)&sAl[row * GLD + seg] = lv;
        }
        for (int i = tid; i < 1024; i += 256) {
            int row = i >> 4, seg = (i & 15) << 2;
            int n = bn + row, k = kc + seg;
            *(uint2*)&sBh[row * GLD + seg] = *(const uint2*)(Bh + (size_t)n * K + k);
            *(uint2*)&sBl[row * GLD + seg] = *(const uint2*)(Bl + (size_t)n * K + k);
        }
        __syncthreads();

#pragma unroll
        for (int ks = 0; ks < 64; ks += 16) {
            uint32_t ah[2][4], al[2][4];
            int ar = lane & 15, ac = (lane >> 4) << 3;
#pragma unroll
            for (int mt = 0; mt < 2; mt++) {
                uint32_t off = (uint32_t)((wm * 32 + mt * 16 + ar) * GLD + ks + ac) * 2;
                ldsm_x4(ah[mt], aAh + off);
                ldsm_x4(al[mt], aAl + off);
            }
            uint32_t bh[4][2], bl[4][2];
            int br = lane & 7, bc = ((lane >> 3) & 1) << 3;
#pragma unroll
            for (int nt = 0; nt < 4; nt++) {
                uint32_t off = (uint32_t)((wn * 32 + nt * 8 + br) * GLD + ks + bc) * 2;
                ldsm_x2(bh[nt], aBh + off);
                ldsm_x2(bl[nt], aBl + off);
            }
#pragma unroll
            for (int mt = 0; mt < 2; mt++)
#pragma unroll
                for (int nt = 0; nt < 4; nt++) {
                    mma_bf16(acc[mt][nt], ah[mt], bh[nt]);
                    mma_bf16(acc[mt][nt], ah[mt], bl[nt]);
                    mma_bf16(acc[mt][nt], al[mt], bh[nt]);
                }
        }
        __syncthreads();
    }

    int rb = bm + wm * 32 + (lane >> 2);
    int cb = bn + wn * 32 + ((lane & 3) << 1);
#pragma unroll
    for (int mt = 0; mt < 2; mt++) {
        int r = rb + mt * 16;
#pragma unroll
        for (int nt = 0; nt < 4; nt++) {
            int c = cb + nt * 8;
            float bx = bias ? bias[c] : 0.f, by = bias ? bias[c + 1] : 0.f;
#pragma unroll
            for (int half = 0; half < 2; half++) {
                int rr = r + half * 8;
                if (rr >= M) continue;
                float v0 = acc[mt][nt][half * 2 + 0] + bx;
                float v1 = acc[mt][nt][half * 2 + 1] + by;
                if (act == 1)      { v0 = fmaxf(v0, 0.f); v1 = fmaxf(v1, 0.f); }
                else if (act == 2) { v0 = 1.f / (1.f + expf(-v0)); v1 = 1.f / (1.f + expf(-v1)); }
                if (C) *(float2*)(C + (size_t)rr * Ntot + c) = make_float2(v0, v1);
                if (H16) {
                    __half2 p = __floats2half2_rn(v0, v1);
                    *(__half2*)(H16 + (size_t)rr * Ntot + c) = p;
                }
                if (Ch) {
                    __nv_bfloat16 h0 = __float2bfloat16(v0), h1 = __float2bfloat16(v1);
                    __nv_bfloat16 l0 = __float2bfloat16(v0 - __bfloat162float(h0));
                    __nv_bfloat16 l1 = __float2bfloat16(v1 - __bfloat162float(h1));
                    *(uint32_t*)(Ch + (size_t)rr * Ntot + c) = pack_bf16(h0, h1);
                    *(uint32_t*)(Cl + (size_t)rr * Ntot + c) = pack_bf16(l0, l1);
                }
            }
        }
    }
}

// ---------------- attention coefficient precompute (f32 h) ---------------------
__global__ void alpha_kernel(const float* __restrict__ h, const float* __restrict__ a_src,
                             const float* __restrict__ a_dst, float* __restrict__ as_,
                             float* __restrict__ ad_, int N, int H)
{
    int gw = (blockIdx.x * blockDim.x + threadIdx.x) >> 5;
    int lane = threadIdx.x & 31;
    if (gw >= N * H) return;
    int n = gw / H, hh = gw - n * H;
    const float4* hp = (const float4*)(h + ((size_t)n * H + hh) * 128);
    const float4* sp = (const float4*)(a_src + hh * 128);
    const float4* dp = (const float4*)(a_dst + hh * 128);
    float4 v = hp[lane], sv = sp[lane], dv = dp[lane];
    float s = v.x * sv.x + v.y * sv.y + v.z * sv.z + v.w * sv.w;
    float d = v.x * dv.x + v.y * dv.y + v.z * dv.z + v.w * dv.w;
#pragma unroll
    for (int o = 16; o; o >>= 1) {
        s += __shfl_xor_sync(0xFFFFFFFFu, s, o);
        d += __shfl_xor_sync(0xFFFFFFFFu, d, o);
    }
    if (lane == 0) { as_[n * H + hh] = s; ad_[n * H + hh] = d; }
}

// ---------------- fused GAT aggregation (one warp per dst node) ----------------
// Gathers messages from the fp16 mirror (half traffic vs f32); accumulates f32.
// Epilogue emits split-bf16 (hi/lo) directly for the next GEMM's A operand.
template<int H, bool DO_BN>
__global__ void gat_agg_kernel(const __half* __restrict__ h16,
                               const float* __restrict__ as_, const float* __restrict__ ad_,
                               const float* __restrict__ bias,
                               const float* __restrict__ bg, const float* __restrict__ bb,
                               const float* __restrict__ bm_, const float* __restrict__ bv,
                               __nv_bfloat16* __restrict__ outh,
                               __nv_bfloat16* __restrict__ outl, int N)
{
    int d = (blockIdx.x * blockDim.x + threadIdx.x) >> 5;
    int lane = threadIdx.x & 31;
    if (d >= N) return;

    float asd[H], add[H];
    if (H == 4) {
        float4 t = ((const float4*)as_)[d];
        asd[0] = t.x; asd[1] = t.y; asd[2] = t.z; asd[3] = t.w;
        t = ((const float4*)ad_)[d];
        add[0] = t.x; add[1] = t.y; add[2] = t.z; add[3] = t.w;
    } else {
        asd[0] = as_[d]; add[0] = ad_[d];
    }

    float acc[H][4];
    float denl[H];
#pragma unroll
    for (int k = 0; k < H; k++) {
        denl[k] = 0.f;
#pragma unroll
        for (int c = 0; c < 4; c++) acc[k][c] = 0.f;
    }

    int r0 = g_off[d], r1 = g_off[d + 1];
    for (int base = r0; base < r1; base += 32) {
        int e = base + lane;
        int s = 0;
        float ex[H];
        if (e < r1) {
            s = g_csr[e];
            float av[H];
            if (H == 4) {
                float4 t = ((const float4*)as_)[s];
                av[0] = t.x; av[1] = t.y; av[2] = t.z; av[3] = t.w;
            } else av[0] = as_[s];
#pragma unroll
            for (int k = 0; k < H; k++) {
                float v = av[k] + add[k];
                v = v > 0.f ? v : 0.2f * v;
                ex[k] = expf(v);
                denl[k] += ex[k];
            }
        } else {
#pragma unroll
            for (int k = 0; k < H; k++) ex[k] = 0.f;
        }
        int cnt = min(32, r1 - base);
        for (int j = 0; j < cnt; j++) {
            int sj = __shfl_sync(0xFFFFFFFFu, s, j);
            const uint2* hp = (const uint2*)(h16 + (size_t)sj * (H * 128));
#pragma unroll
            for (int k = 0; k < H; k++) {
                float exj = __shfl_sync(0xFFFFFFFFu, ex[k], j);
                uint2 u = hp[k * 32 + lane];
                float2 f0 = __half22float2(*(__half2*)&u.x);
                float2 f1 = __half22float2(*(__half2*)&u.y);
                acc[k][0] += exj * f0.x;
                acc[k][1] += exj * f0.y;
                acc[k][2] += exj * f1.x;
                acc[k][3] += exj * f1.y;
            }
        }
    }

    const uint2* hpd = (const uint2*)(h16 + (size_t)d * (H * 128));
#pragma unroll
    for (int k = 0; k < H; k++) {
        float v = asd[k] + add[k];
        v = v > 0.f ? v : 0.2f * v;
        float exs = expf(v);
        uint2 u = hpd[k * 32 + lane];
        float2 f0 = __half22float2(*(__half2*)&u.x);
        float2 f1 = __half22float2(*(__half2*)&u.y);
        acc[k][0] += exs * f0.x;
        acc[k][1] += exs * f0.y;
        acc[k][2] += exs * f1.x;
        acc[k][3] += exs * f1.y;
        float dk = denl[k];
#pragma unroll
        for (int o = 16; o; o >>= 1) dk += __shfl_xor_sync(0xFFFFFFFFu, dk, o);
        denl[k] = dk + exs;
    }

    float v0 = 0.f, v1 = 0.f, v2 = 0.f, v3 = 0.f;
#pragma unroll
    for (int k = 0; k < H; k++) {
        float r = 1.f / (denl[k] + 1e-16f);
        v0 += acc[k][0] * r;
        v1 += acc[k][1] * r;
        v2 += acc[k][2] * r;
        v3 += acc[k][3] * r;
    }
    if (H == 4) { v0 *= 0.25f; v1 *= 0.25f; v2 *= 0.25f; v3 *= 0.25f; }

    int c0 = lane * 4;
    float4 bz = *(const float4*)(bias + c0);
    v0 += bz.x; v1 += bz.y; v2 += bz.z; v3 += bz.w;

    if (DO_BN) {
        float4 gg = *(const float4*)(bg + c0);
        float4 bb4 = *(const float4*)(bb + c0);
        float4 mm = *(const float4*)(bm_ + c0);
        float4 vv = *(const float4*)(bv + c0);
        v0 = fmaxf(gg.x * (v0 - mm.x) * rsqrtf(vv.x + 1e-5f) + bb4.x, 0.f);
        v1 = fmaxf(gg.y * (v1 - mm.y) * rsqrtf(vv.y + 1e-5f) + bb4.y, 0.f);
        v2 = fmaxf(gg.z * (v2 - mm.z) * rsqrtf(vv.z + 1e-5f) + bb4.z, 0.f);
        v3 = fmaxf(gg.w * (v3 - mm.w) * rsqrtf(vv.w + 1e-5f) + bb4.w, 0.f);
    }

    __nv_bfloat16 h0 = __float2bfloat16(v0), h1 = __float2bfloat16(v1);
    __nv_bfloat16 h2 = __float2bfloat16(v2), h3 = __float2bfloat16(v3);
    __nv_bfloat16 l0 = __float2bfloat16(v0 - __bfloat162float(h0));
    __nv_bfloat16 l1 = __float2bfloat16(v1 - __bfloat162float(h1));
    __nv_bfloat16 l2 = __float2bfloat16(v2 - __bfloat162float(h2));
    __nv_bfloat16 l3 = __float2bfloat16(v3 - __bfloat162float(h3));
    *(uint2*)(outh + (size_t)d * 128 + c0) = make_uint2(pack_bf16(h0, h1), pack_bf16(h2, h3));
    *(uint2*)(outl + (size_t)d * 128 + c0) = make_uint2(pack_bf16(l0, l1), pack_bf16(l2, l3));
}

// ---------------- host-side orchestration -------------------------------------
static void launch_gemm(const __nv_bfloat16* Ah, const __nv_bfloat16* Al,
                        const __nv_bfloat16* Bh, const __nv_bfloat16* Bl,
                        const float* bias, float* C, __half* H16,
                        __nv_bfloat16* Ch, __nv_bfloat16* Cl,
                        int M, int Ntot, int K, int act)
{
    static bool attr_set = false;
    size_t smem = (size_t)(128 + 128 + 64 + 64) * GLD * sizeof(__nv_bfloat16);
    if (!attr_set) {
        cudaFuncSetAttribute(mma_gemm_kernel, cudaFuncAttributeMaxDynamicSharedMemorySize,
                             (int)smem);
        attr_set = true;
    }
    dim3 grid(Ntot / 64, (M + 127) / 128);
    mma_gemm_kernel<<<grid, 256, smem>>>(Ah, Al, Bh, Bl, bias, C, H16, Ch, Cl, M, Ntot, K, act);
}

extern "C" void kernel_launch(void* const* d_in, const int* in_sizes, int n_in,
                              void* d_out, int out_size)
{
    const float* x   = (const float*)d_in[0];
    const int*   ei  = (const int*)  d_in[1];
    const float* W1  = (const float*)d_in[2];
    const float* as1 = (const float*)d_in[3];
    const float* ad1 = (const float*)d_in[4];
    const float* b1  = (const float*)d_in[5];
    const float* W2  = (const float*)d_in[6];
    const float* as2 = (const float*)d_in[7];
    const float* ad2 = (const float*)d_in[8];
    const float* b2  = (const float*)d_in[9];
    const float* W3  = (const float*)d_in[10];
    const float* as3 = (const float*)d_in[11];
    const float* ad3 = (const float*)d_in[12];
    const float* b3  = (const float*)d_in[13];
    const float* bn1g = (const float*)d_in[14];
    const float* bn1b = (const float*)d_in[15];
    const float* bn1m = (const float*)d_in[16];
    const float* bn1v = (const float*)d_in[17];
    const float* bn2g = (const float*)d_in[18];
    const float* bn2b = (const float*)d_in[19];
    const float* bn2m = (const float*)d_in[20];
    const float* bn2v = (const float*)d_in[21];
    const float* l1w = (const float*)d_in[22];
    const float* l1b = (const float*)d_in[23];
    const float* l2w = (const float*)d_in[24];
    const float* l2b = (const float*)d_in[25];
    const float* l3w = (const float*)d_in[26];
    const float* l3b = (const float*)d_in[27];

    const int N = in_sizes[0] / 256;       // 20000
    const int E = in_sizes[1] / 2;         // 320000
    const int* src = ei;
    const int* dst = ei + E;

    float *h, *as_, *ad_;
    __half *h16;
    __nv_bfloat16 *ah, *al, *ah2, *al2, *bh, *bl;
    cudaGetSymbolAddress((void**)&h,   g_h);
    cudaGetSymbolAddress((void**)&h16, g_h16);
    cudaGetSymbolAddress((void**)&as_, g_as);
    cudaGetSymbolAddress((void**)&ad_, g_ad);
    cudaGetSymbolAddress((void**)&ah,  g_ah);
    cudaGetSymbolAddress((void**)&al,  g_al);
    cudaGetSymbolAddress((void**)&ah2, g_ah2);
    cudaGetSymbolAddress((void**)&al2, g_al2);
    cudaGetSymbolAddress((void**)&bh,  g_bh);
    cudaGetSymbolAddress((void**)&bl,  g_bl);

    // ---- CSR build + all-weight split ----
    zero_deg_kernel<<<(N + 255) / 256, 256>>>(N);
    hist_kernel<<<(E + 255) / 256, 256>>>(dst, E);
    scan_kernel<<<1, 1024>>>(N);
    scatter_kernel<<<(E + 255) / 256, 256>>>(src, dst, E);
    splitT_all_kernel<<<(OFF_L3 + 4096 + 255) / 256, 256>>>(W1, W2, W3, l1w, l2w, l3w);

    int agg_blocks = (N * 32 + 255) / 256;

    // ---- GAT layer 1 (heads=4, mean) + BN1 + relu ----
    split_kernel<<<(N * 256 + 255) / 256, 256>>>(x, ah, al, N * 256);
    launch_gemm(ah, al, bh + OFF_W1, bl + OFF_W1, nullptr, h, h16, nullptr, nullptr, N, 512, 256, 0);
    alpha_kernel<<<(N * 4 * 32 + 255) / 256, 256>>>(h, as1, ad1, as_, ad_, N, 4);
    gat_agg_kernel<4, true><<<agg_blocks, 256>>>(h16, as_, ad_, b1, bn1g, bn1b, bn1m, bn1v, ah2, al2, N);

    // ---- GAT layer 2 (heads=4, mean) + BN2 + relu ----
    launch_gemm(ah2, al2, bh + OFF_W2, bl + OFF_W2, nullptr, h, h16, nullptr, nullptr, N, 512, 128, 0);
    alpha_kernel<<<(N * 4 * 32 + 255) / 256, 256>>>(h, as2, ad2, as_, ad_, N, 4);
    gat_agg_kernel<4, true><<<agg_blocks, 256>>>(h16, as_, ad_, b2, bn2g, bn2b, bn2m, bn2v, ah, al, N);

    // ---- GAT layer 3 (heads=1, concat) ----
    launch_gemm(ah, al, bh + OFF_W3, bl + OFF_W3, nullptr, h, h16, nullptr, nullptr, N, 128, 128, 0);
    alpha_kernel<<<(N * 32 + 255) / 256, 256>>>(h, as3, ad3, as_, ad_, N, 1);
    gat_agg_kernel<1, false><<<agg_blocks, 256>>>(h16, as_, ad_, b3, nullptr, nullptr, nullptr, nullptr, ah2, al2, N);

    // ---- classifier MLP (split-bf16 flows through epilogues) ----
    launch_gemm(ah2, al2, bh + OFF_L1, bl + OFF_L1, l1b, nullptr, nullptr, ah, al, N, 128, 128, 1);
    launch_gemm(ah, al, bh + OFF_L2, bl + OFF_L2, l2b, nullptr, nullptr, ah2, al2, N, 64, 128, 1);
    launch_gemm(ah2, al2, bh + OFF_L3, bl + OFF_L3, l3b, (float*)d_out, nullptr, nullptr, nullptr, N, 64, 64, 2);
}